// round 10
// baseline (speedup 1.0000x reference)
#include <cuda_runtime.h>
#include <cstdint>

// HungarianMatcher cost matrix, diagonal only.
//   out[b,q,t] = |cq-ct|+|wq-wt| - softmax(logits[b,q])[label_t] - gIoU(scaled)
//
// BW-concurrency-bound regime: cp.async double-buffered row staging (loads
// don't hold registers), persistent grid with cross-chunk software pipeline,
// warp-private buffers (no block barriers), fast divides.

#define BS 64
#define NQ 300
#define NC 200
#define NT 32
#define THREADS 256
#define WARPS 8
#define QCHUNKS ((NQ + WARPS - 1) / WARPS)   // 38 chunks of 8 rows per batch
#define NCHUNKS (BS * QCHUNKS)               // 2432
#define GRID    888                          // 6 resident blocks x 148 SMs

__global__ __launch_bounds__(THREADS, 6)
void matcher_kernel(const float* __restrict__ logits,
                    const float* __restrict__ pred_seg,
                    const float* __restrict__ tgt_seg,
                    const float* __restrict__ lengths,
                    const int*   __restrict__ labels32,
                    float* __restrict__ out)
{
    __shared__ __align__(16) float s_rows[2][WARPS][NC];   // 12.8 KB

    const int warp = threadIdx.x >> 5;
    const int lane = threadIdx.x & 31;

    // Label dtype probe on batch 0 (JAX silently demotes int64->int32).
    const int plo = labels32[2 * lane];
    const int phi = labels32[2 * lane + 1];
    const bool ok64 = (phi == 0) && ((unsigned)plo < (unsigned)NC);
    const bool is64 = (__ballot_sync(0xffffffffu, ok64) == 0xffffffffu);

    uint32_t sb0 = (uint32_t)__cvta_generic_to_shared(&s_rows[0][warp][0]);
    uint32_t sb1 = (uint32_t)__cvta_generic_to_shared(&s_rows[1][warp][0]);

    // Issue this warp's row of chunk c into smem buffer p via cp.async.
    // Row = 800B = 50 x 16B: lanes 0..31 copy chunk 'lane', lanes 0..17 also
    // copy chunk 'lane+32'. Always commits a group (possibly empty).
    auto issue = [&](int c, int p) {
        const int bb = c / QCHUNKS;
        const int qq = (c - bb * QCHUNKS) * WARPS + warp;
        if (qq < NQ) {
            const char* src =
                (const char*)(logits + ((size_t)bb * NQ + qq) * NC);
            const uint32_t d = p ? sb1 : sb0;
            asm volatile("cp.async.cg.shared.global [%0], [%1], 16;\n"
                         :: "r"(d + lane * 16), "l"(src + lane * 16));
            if (lane < 18)
                asm volatile("cp.async.cg.shared.global [%0], [%1], 16;\n"
                             :: "r"(d + (lane + 32) * 16),
                                "l"(src + (lane + 32) * 16));
        }
        asm volatile("cp.async.commit_group;\n" ::: "memory");
    };

    // Scalar/aux loads for chunk c (regular LDG, in flight during compute).
    auto aux_load = [&](int c, float2& sg, float2& tsg, float& L,
                        int& lab, int& q, int& b) {
        b = c / QCHUNKS;
        q = (c - b * QCHUNKS) * WARPS + warp;
        if (q < NQ) {
            L   = lengths[b];
            sg  = ((const float2*)pred_seg)[(size_t)b * NQ + q];
            const int idx = b * NT + lane;
            tsg = ((const float2*)tgt_seg)[idx];
            lab = is64 ? labels32[2 * idx] : labels32[idx];
        } else {
            q = -1; L = 1.f; lab = 0;
            sg = make_float2(0.f, 0.f); tsg = sg;
        }
    };

    int c = blockIdx.x;
    int p = 0;
    issue(c, 0);
    float2 sg, tsg; float L; int lab, q, b;
    aux_load(c, sg, tsg, L, lab, q, b);

    while (true) {
        const int  cn  = c + GRID;
        const bool pre = cn < NCHUNKS;
        float2 sgn, tsgn; float Ln = 1.f; int labn = 0, qn = -1, bn = 0;
        sgn = make_float2(0.f, 0.f); tsgn = sgn;
        if (pre) {
            issue(cn, p ^ 1);                       // prefetch next chunk row
            aux_load(cn, sgn, tsgn, Ln, labn, qn, bn);
        }

        // Wait for THIS chunk's group (allow the prefetch to stay in flight).
        if (pre) asm volatile("cp.async.wait_group 1;\n" ::: "memory");
        else     asm volatile("cp.async.wait_group 0;\n" ::: "memory");
        __syncwarp();  // all lanes' copies complete before cross-lane reads

        if (q >= 0) {
            const float*  row = s_rows[p][warp];
            const float4* r4  = (const float4*)row;

            // exps + denominator
            float4 a0 = r4[lane];
            float4 e;
            e.x = __expf(a0.x); e.y = __expf(a0.y);
            e.z = __expf(a0.z); e.w = __expf(a0.w);
            float sum = (e.x + e.y) + (e.z + e.w);
            if (lane < 18) {
                float4 a1 = r4[lane + 32];
                e.x = __expf(a1.x); e.y = __expf(a1.y);
                e.z = __expf(a1.z); e.w = __expf(a1.w);
                sum += (e.x + e.y) + (e.z + e.w);
            }
            #pragma unroll
            for (int off = 16; off; off >>= 1)
                sum += __shfl_xor_sync(0xffffffffu, sum, off);

            const float g   = row[lab];                      // smem gather
            const float cls = -__fdividef(__expf(g), sum);

            // pair costs: lane t handles target t
            const float cq = sg.x,  wq = sg.y;
            const float tc = tsg.x, tw = tsg.y;
            const float cqs = cq * L, wqs = wq * L;
            const float s1  = cqs - 0.5f * wqs;
            const float e1v = cqs + 0.5f * wqs;
            const float tcs = tc * L, tws = tw * L;
            const float s2  = tcs - 0.5f * tws;
            const float e2v = tcs + 0.5f * tws;
            float inter = fmaxf(fminf(e1v, e2v) - fmaxf(s1, s2), 0.f);
            const float uni  = (e1v - s1) + (e2v - s2) - inter;
            const float enc  = fmaxf(e1v, e2v) - fminf(s1, s2);
            const float giou = __fdividef(inter, uni)
                             - __fdividef(enc - uni, enc);

            out[((size_t)b * NQ + q) * NT + lane] =
                fabsf(cq - tc) + fabsf(wq - tw) + cls - giou;
        }
        __syncwarp();  // finish reading buf p before it's refilled next iter

        if (!pre) break;
        c = cn; p ^= 1;
        sg = sgn; tsg = tsgn; L = Ln; lab = labn; q = qn; b = bn;
    }
}

extern "C" void kernel_launch(void* const* d_in, const int* in_sizes, int n_in,
                              void* d_out, int out_size)
{
    const float* logits   = (const float*)d_in[0];
    const float* pred_seg = (const float*)d_in[1];
    const float* tgt_seg  = (const float*)d_in[2];
    const float* lengths  = (const float*)d_in[3];
    const int*   labels   = (const int*)d_in[4];
    float*       out      = (float*)d_out;

    matcher_kernel<<<GRID, THREADS>>>(logits, pred_seg, tgt_seg, lengths,
                                      labels, out);
}

// round 12
// speedup vs baseline: 1.1910x; 1.1910x over previous
#include <cuda_runtime.h>
#include <cstdint>

// HungarianMatcher cost matrix, diagonal only.
//   out[b,q,t] = |cq-ct|+|wq-wt| - softmax(logits[b,q])[label_t] - gIoU(scaled)
//
// Deep cp.async pipeline: 2 rows/warp/chunk staged in smem, exactly 2 chunks
// per block (issue both up front, two-stage drain), interleaved 2-row compute.

#define BS 64
#define NQ 300
#define NC 200
#define NT 32
#define THREADS 256
#define WARPS 8
#define RPW 2                              // rows per warp per chunk
#define RPC (WARPS * RPW)                  // 16 rows per chunk
#define QCHUNKS ((NQ + RPC - 1) / RPC)     // 19
#define NCHUNKS (BS * QCHUNKS)             // 1216
#define GRID (NCHUNKS / 2)                 // 608, 2 chunks per block

__global__ __launch_bounds__(THREADS, 4)
void matcher_kernel(const float* __restrict__ logits,
                    const float* __restrict__ pred_seg,
                    const float* __restrict__ tgt_seg,
                    const float* __restrict__ lengths,
                    const int*   __restrict__ labels32,
                    float* __restrict__ out)
{
    __shared__ __align__(16) float s_rows[2][WARPS][RPW][NC];   // 25.6 KB

    const int warp = threadIdx.x >> 5;
    const int lane = threadIdx.x & 31;

    // Label dtype probe on batch 0 (JAX silently demotes int64->int32).
    const int plo = labels32[2 * lane];
    const int phi = labels32[2 * lane + 1];
    const bool ok64 = (phi == 0) && ((unsigned)plo < (unsigned)NC);
    const bool is64 = (__ballot_sync(0xffffffffu, ok64) == 0xffffffffu);

    const int c0 = blockIdx.x * 2;
    const int c1 = c0 + 1;

    // ---- stage both chunks' rows via cp.async (one group per chunk) ----
    auto issue = [&](int c, int p) {
        const int bb = c / QCHUNKS;
        const int qb = (c - bb * QCHUNKS) * RPC + RPW * warp;
        #pragma unroll
        for (int r = 0; r < RPW; ++r) {
            const int q = qb + r;
            if (q < NQ) {
                const char* src =
                    (const char*)(logits + ((size_t)bb * NQ + q) * NC);
                const uint32_t d = (uint32_t)
                    __cvta_generic_to_shared(&s_rows[p][warp][r][0]);
                asm volatile("cp.async.cg.shared.global [%0], [%1], 16;\n"
                             :: "r"(d + lane * 16), "l"(src + lane * 16));
                if (lane < 18)
                    asm volatile("cp.async.cg.shared.global [%0], [%1], 16;\n"
                                 :: "r"(d + (lane + 32) * 16),
                                    "l"(src + (lane + 32) * 16));
            } else {
                // tail hygiene: zero the unused staging row so later
                // speculative exps read finite values (results never stored)
                float4* dst = (float4*)&s_rows[p][warp][r][0];
                dst[lane] = make_float4(0.f, 0.f, 0.f, 0.f);
                if (lane < 18)
                    dst[lane + 32] = make_float4(0.f, 0.f, 0.f, 0.f);
            }
        }
        asm volatile("cp.async.commit_group;\n" ::: "memory");
    };
    issue(c0, 0);
    issue(c1, 1);

    // ---- aux loads for both chunks (LDGs overlap the async copies) ----
    int   b[2], qb[2], lab[2];
    float L[2];
    float2 sg0[2], sg1[2], tsg[2];
    #pragma unroll
    for (int k = 0; k < 2; ++k) {
        const int c = c0 + k;
        b[k]  = c / QCHUNKS;
        qb[k] = (c - b[k] * QCHUNKS) * RPC + RPW * warp;
        L[k]  = lengths[b[k]];
        const int q0 = qb[k];
        sg0[k] = (q0 < NQ)     ? ((const float2*)pred_seg)[(size_t)b[k] * NQ + q0]
                               : make_float2(0.f, 0.f);
        sg1[k] = (q0 + 1 < NQ) ? ((const float2*)pred_seg)[(size_t)b[k] * NQ + q0 + 1]
                               : make_float2(0.f, 0.f);
        const int idx = b[k] * NT + lane;
        tsg[k] = ((const float2*)tgt_seg)[idx];
        lab[k] = is64 ? labels32[2 * idx] : labels32[idx];
    }

    // ---- compute one chunk from smem buffer p ----
    auto compute = [&](int k, int p) {
        const int q0 = qb[k];
        const int q1 = q0 + 1;
        const bool v0 = q0 < NQ;
        const bool v1 = q1 < NQ;
        if (!v0) return;

        const float*  row0 = s_rows[p][warp][0];
        const float*  row1 = s_rows[p][warp][1];
        const float4* r40  = (const float4*)row0;
        const float4* r41  = (const float4*)row1;

        // interleaved exps + denominators for both rows (ILP)
        float4 x0 = r40[lane];
        float4 x1 = r41[lane];
        float4 e;
        e.x = __expf(x0.x); e.y = __expf(x0.y);
        e.z = __expf(x0.z); e.w = __expf(x0.w);
        float s0 = (e.x + e.y) + (e.z + e.w);
        e.x = __expf(x1.x); e.y = __expf(x1.y);
        e.z = __expf(x1.z); e.w = __expf(x1.w);
        float s1 = (e.x + e.y) + (e.z + e.w);
        if (lane < 18) {
            float4 y0 = r40[lane + 32];
            float4 y1 = r41[lane + 32];
            e.x = __expf(y0.x); e.y = __expf(y0.y);
            e.z = __expf(y0.z); e.w = __expf(y0.w);
            s0 += (e.x + e.y) + (e.z + e.w);
            e.x = __expf(y1.x); e.y = __expf(y1.y);
            e.z = __expf(y1.z); e.w = __expf(y1.w);
            s1 += (e.x + e.y) + (e.z + e.w);
        }
        #pragma unroll
        for (int off = 16; off; off >>= 1) {
            s0 += __shfl_xor_sync(0xffffffffu, s0, off);
            s1 += __shfl_xor_sync(0xffffffffu, s1, off);
        }
        const float cls0 = -__fdividef(__expf(row0[lab[k]]), s0);
        const float cls1 = -__fdividef(__expf(row1[lab[k]]), s1);

        // target scaled once per chunk
        const float Lb  = L[k];
        const float tc  = tsg[k].x, tw = tsg[k].y;
        const float tcs = tc * Lb,  tws = tw * Lb;
        const float s2  = tcs - 0.5f * tws;
        const float e2  = tcs + 0.5f * tws;
        const float tlen = e2 - s2;

        {   // row q0
            const float cq = sg0[k].x, wq = sg0[k].y;
            const float cqs = cq * Lb, wqs = wq * Lb;
            const float a = cqs - 0.5f * wqs;
            const float z = cqs + 0.5f * wqs;
            float inter = fmaxf(fminf(z, e2) - fmaxf(a, s2), 0.f);
            const float uni = (z - a) + tlen - inter;
            const float enc = fmaxf(z, e2) - fminf(a, s2);
            const float giou = __fdividef(inter, uni)
                             - __fdividef(enc - uni, enc);
            out[((size_t)b[k] * NQ + q0) * NT + lane] =
                fabsf(cq - tc) + fabsf(wq - tw) + cls0 - giou;
        }
        if (v1) {   // row q1
            const float cq = sg1[k].x, wq = sg1[k].y;
            const float cqs = cq * Lb, wqs = wq * Lb;
            const float a = cqs - 0.5f * wqs;
            const float z = cqs + 0.5f * wqs;
            float inter = fmaxf(fminf(z, e2) - fmaxf(a, s2), 0.f);
            const float uni = (z - a) + tlen - inter;
            const float enc = fmaxf(z, e2) - fminf(a, s2);
            const float giou = __fdividef(inter, uni)
                             - __fdividef(enc - uni, enc);
            out[((size_t)b[k] * NQ + q1) * NT + lane] =
                fabsf(cq - tc) + fabsf(wq - tw) + cls1 - giou;
        }
    };

    // ---- two-stage drain ----
    asm volatile("cp.async.wait_group 1;\n" ::: "memory");
    __syncwarp();
    compute(0, 0);
    asm volatile("cp.async.wait_group 0;\n" ::: "memory");
    __syncwarp();
    compute(1, 1);
}

extern "C" void kernel_launch(void* const* d_in, const int* in_sizes, int n_in,
                              void* d_out, int out_size)
{
    const float* logits   = (const float*)d_in[0];
    const float* pred_seg = (const float*)d_in[1];
    const float* tgt_seg  = (const float*)d_in[2];
    const float* lengths  = (const float*)d_in[3];
    const int*   labels   = (const int*)d_in[4];
    float*       out      = (float*)d_out;

    matcher_kernel<<<GRID, THREADS>>>(logits, pred_seg, tgt_seg, lengths,
                                      labels, out);
}